// round 14
// baseline (speedup 1.0000x reference)
#include <cuda_runtime.h>
#include <cuda_bf16.h>
#include <cuda_fp16.h>
#include <math.h>
#include <cstdint>

#define NN 50000
#define EE 800000
#define NH 8

// ---------------- scratch (device globals; no runtime allocation) ----------------
__device__ __align__(16) float g_agg  [NN * 256];
__device__ __align__(16) float g_ssrc [NN * NH];
__device__ __align__(16) float g_sdst [NN * NH];
__device__ __align__(16) float g_denom[NN * NH];
__device__ float g_emb  [NN * 3 * 256];
__device__ float g_hid  [NN * 3 * 128];
__device__ float g_hcls [NN * 128];

__device__ __align__(16) __half g_hp16[NN * 256];

__device__ __align__(16) __nv_bfloat16 g_xhi [NN * 128];
__device__ __align__(16) __nv_bfloat16 g_xlo [NN * 128];
__device__ __align__(16) __nv_bfloat16 g_h0hi[NN * 256];
__device__ __align__(16) __nv_bfloat16 g_h0lo[NN * 256];
__device__ __align__(16) __nv_bfloat16 g_hhi [NN * 256];
__device__ __align__(16) __nv_bfloat16 g_hlo [NN * 256];
__device__ __align__(16) __nv_bfloat16 g_ehi [NN * 3 * 256];
__device__ __align__(16) __nv_bfloat16 g_elo [NN * 3 * 256];
__device__ __align__(16) __nv_bfloat16 g_zhi [NN * 256];
__device__ __align__(16) __nv_bfloat16 g_zlo [NN * 256];
// transposed+split weights [N][K]
__device__ __align__(16) __nv_bfloat16 g_whi [491520];
__device__ __align__(16) __nv_bfloat16 g_wlo [491520];

// ---------------- warp-MMA + cp.async helpers (plain sm_80+ PTX) ----------------
__device__ __forceinline__ uint32_t smem_u32(const void* p) {
    uint32_t a;
    asm("{ .reg .u64 t; cvta.to.shared.u64 t, %1; cvt.u32.u64 %0, t; }" : "=r"(a) : "l"(p));
    return a;
}
__device__ __forceinline__ void ldsm_x4(uint32_t* r, uint32_t addr) {
    asm volatile("ldmatrix.sync.aligned.m8n8.x4.shared.b16 {%0,%1,%2,%3}, [%4];"
                 : "=r"(r[0]), "=r"(r[1]), "=r"(r[2]), "=r"(r[3]) : "r"(addr));
}
__device__ __forceinline__ void ldsm_x2(uint32_t* r, uint32_t addr) {
    asm volatile("ldmatrix.sync.aligned.m8n8.x2.shared.b16 {%0,%1}, [%2];"
                 : "=r"(r[0]), "=r"(r[1]) : "r"(addr));
}
__device__ __forceinline__ void mma_bf16(float* c, const uint32_t* a, const uint32_t* b) {
    asm volatile("mma.sync.aligned.m16n8k16.row.col.f32.bf16.bf16.f32 "
                 "{%0,%1,%2,%3}, {%4,%5,%6,%7}, {%8,%9}, {%0,%1,%2,%3};"
                 : "+f"(c[0]), "+f"(c[1]), "+f"(c[2]), "+f"(c[3])
                 : "r"(a[0]), "r"(a[1]), "r"(a[2]), "r"(a[3]), "r"(b[0]), "r"(b[1]));
}
__device__ __forceinline__ void cp16(uint32_t saddr, const void* g, int srcsize) {
    asm volatile("cp.async.cg.shared.global [%0], [%1], 16, %2;"
                 :: "r"(saddr), "l"(g), "r"(srcsize) : "memory");
}
#define CP_COMMIT() asm volatile("cp.async.commit_group;" ::: "memory")
#define CP_WAIT(n)  asm volatile("cp.async.wait_group %0;" :: "n"(n) : "memory")

// ---------------- bf16-split tensor GEMM, cp.async double-buffered ----------------
// D ~= Ahi*Bhi + Ahi*Blo + Alo*Bhi (fp32 accum). A = hi+lo bf16 [M,K]; W split [Nc][K].
// EPI: 0 = fp32 C (+bias+act), 1 = split bf16 hi/lo C (+bias), 2 = GAT (write fp16 hp,
//      fused attention logits: atomicAdd ssrc/sdst partial dot products).
#define LDSE   40
#define PLANE  10240
#define BUFSZ  20480
#define BHALF  40960
#define SMEMSZ 81920
template <int EPI, int ACT>   // ACT: 0 none, 1 tanh, 2 relu
__global__ void __launch_bounds__(256, 1)
gemm_mma(const __nv_bfloat16* __restrict__ Ahi, const __nv_bfloat16* __restrict__ Alo,
         const __nv_bfloat16* __restrict__ Bhi, const __nv_bfloat16* __restrict__ Blo,
         const float* __restrict__ bias,
         float* __restrict__ C, __nv_bfloat16* __restrict__ Chi,
         __nv_bfloat16* __restrict__ Clo,
         __half* __restrict__ H16,
         const float* __restrict__ asrc, const float* __restrict__ adst,
         float* __restrict__ Ssrc, float* __restrict__ Sdst,
         int M, int K, int Nc) {
    extern __shared__ __align__(16) char smem[];
    const uint32_t sAu = smem_u32(smem);
    const uint32_t sBu = sAu + BHALF;
    const int tid = threadIdx.x;
    const int lane = tid & 31;
    const int w = tid >> 5;
    const int wm = w & 3, wn = w >> 2;
    const int rowBase = blockIdx.y * 128;
    const int colBase = blockIdx.x * 128;

    float acc[2][8][4];
#pragma unroll
    for (int i = 0; i < 2; i++)
#pragma unroll
        for (int j = 0; j < 8; j++)
#pragma unroll
            for (int e = 0; e < 4; e++) acc[i][j][e] = 0.f;

    auto load_tile = [&](int buf, int k0) {
#pragma unroll
        for (int t = 0; t < 2; t++) {
            const int idx = tid + t * 256;
            const int row = idx >> 2;
            const int cb  = (idx & 3) * 16;
            const uint32_t soff = (uint32_t)(row * (LDSE * 2) + cb);
            const int grow = rowBase + row;
            const int ar = grow < M ? grow : (M - 1);
            const int ssz = grow < M ? 16 : 0;
            const char* gah = (const char*)Ahi + ((size_t)ar * K + k0) * 2 + cb;
            const char* gal = (const char*)Alo + ((size_t)ar * K + k0) * 2 + cb;
            cp16(sAu + buf * BUFSZ + soff,          gah, ssz);
            cp16(sAu + buf * BUFSZ + PLANE + soff,  gal, ssz);
            const int gn = colBase + row;
            const char* gbh = (const char*)Bhi + ((size_t)gn * K + k0) * 2 + cb;
            const char* gbl = (const char*)Blo + ((size_t)gn * K + k0) * 2 + cb;
            cp16(sBu + buf * BUFSZ + soff,          gbh, 16);
            cp16(sBu + buf * BUFSZ + PLANE + soff,  gbl, 16);
        }
    };

    const int ntiles = K >> 5;
    load_tile(0, 0);
    CP_COMMIT();

    for (int c = 0; c < ntiles; c++) {
        const int cur = c & 1;
        if (c + 1 < ntiles) {
            load_tile(cur ^ 1, (c + 1) << 5);
            CP_COMMIT();
            CP_WAIT(1);
        } else {
            CP_WAIT(0);
        }
        __syncthreads();

        const uint32_t aB = sAu + cur * BUFSZ;
        const uint32_t bB = sBu + cur * BUFSZ;
#pragma unroll
        for (int k16 = 0; k16 < 2; k16++) {
            uint32_t ahi[2][4], alo[2][4];
#pragma unroll
            for (int mt = 0; mt < 2; mt++) {
                const uint32_t ra = aB +
                    (uint32_t)((wm * 32 + mt * 16 + (lane & 15)) * (LDSE * 2)
                               + k16 * 32 + (lane >> 4) * 16);
                ldsm_x4(ahi[mt], ra);
                ldsm_x4(alo[mt], ra + PLANE);
            }
#pragma unroll
            for (int nt = 0; nt < 8; nt++) {
                const uint32_t rb = bB +
                    (uint32_t)((wn * 64 + nt * 8 + (lane & 7)) * (LDSE * 2)
                               + k16 * 32 + ((lane >> 3) & 1) * 16);
                uint32_t bhi[2], blo[2];
                ldsm_x2(bhi, rb);
                ldsm_x2(blo, rb + PLANE);
#pragma unroll
                for (int mt = 0; mt < 2; mt++) {
                    mma_bf16(acc[mt][nt], ahi[mt], bhi);
                    mma_bf16(acc[mt][nt], ahi[mt], blo);
                    mma_bf16(acc[mt][nt], alo[mt], bhi);
                }
            }
        }
        __syncthreads();
    }

    const int g = lane >> 2, tq = lane & 3;
    if (EPI == 2) {
        // GAT epilogue: write fp16 hp; accumulate attention logit partials.
        const int headbase = blockIdx.x * 4 + wn * 2;
#pragma unroll
        for (int mt = 0; mt < 2; mt++) {
#pragma unroll
            for (int half = 0; half < 2; half++) {
                const int row = rowBase + wm * 32 + mt * 16 + g + half * 8;
                float ps0 = 0.f, ps1 = 0.f, pd0 = 0.f, pd1 = 0.f;
                if (row < M) {
#pragma unroll
                    for (int nt = 0; nt < 8; nt++) {
                        const int col = colBase + wn * 64 + nt * 8 + tq * 2;
                        const float v0 = acc[mt][nt][half * 2 + 0];
                        const float v1 = acc[mt][nt][half * 2 + 1];
                        *(__half2*)(H16 + (size_t)row * 256 + col) =
                            __floats2half2_rn(v0, v1);
                        const float a0s = __ldg(&asrc[col]), a1s = __ldg(&asrc[col + 1]);
                        const float a0d = __ldg(&adst[col]), a1d = __ldg(&adst[col + 1]);
                        if (nt < 4) { ps0 += v0 * a0s + v1 * a1s; pd0 += v0 * a0d + v1 * a1d; }
                        else        { ps1 += v0 * a0s + v1 * a1s; pd1 += v0 * a0d + v1 * a1d; }
                    }
                }
                ps0 += __shfl_down_sync(0xffffffffu, ps0, 2);
                ps0 += __shfl_down_sync(0xffffffffu, ps0, 1);
                ps1 += __shfl_down_sync(0xffffffffu, ps1, 2);
                ps1 += __shfl_down_sync(0xffffffffu, ps1, 1);
                pd0 += __shfl_down_sync(0xffffffffu, pd0, 2);
                pd0 += __shfl_down_sync(0xffffffffu, pd0, 1);
                pd1 += __shfl_down_sync(0xffffffffu, pd1, 2);
                pd1 += __shfl_down_sync(0xffffffffu, pd1, 1);
                if (tq == 0 && row < M) {
                    atomicAdd(&Ssrc[row * NH + headbase + 0], ps0);
                    atomicAdd(&Ssrc[row * NH + headbase + 1], ps1);
                    atomicAdd(&Sdst[row * NH + headbase + 0], pd0);
                    atomicAdd(&Sdst[row * NH + headbase + 1], pd1);
                }
            }
        }
    } else {
#pragma unroll
        for (int mt = 0; mt < 2; mt++) {
#pragma unroll
            for (int nt = 0; nt < 8; nt++) {
                const int col = colBase + wn * 64 + nt * 8 + tq * 2;
#pragma unroll
                for (int half = 0; half < 2; half++) {
                    const int row = rowBase + wm * 32 + mt * 16 + g + half * 8;
                    if (row < M) {
#pragma unroll
                        for (int e = 0; e < 2; e++) {
                            float v = acc[mt][nt][half * 2 + e];
                            const int c = col + e;
                            if (bias) v += bias[c];
                            if (ACT == 1) v = tanhf(v);
                            else if (ACT == 2) v = fmaxf(v, 0.f);
                            const size_t o = (size_t)row * Nc + c;
                            if (EPI == 1) {
                                const __nv_bfloat16 h = __float2bfloat16(v);
                                Chi[o] = h;
                                Clo[o] = __float2bfloat16(v - __bfloat162float(h));
                            } else {
                                C[o] = v;
                            }
                        }
                    }
                }
            }
        }
    }
}

// ---------------- weight transpose + split ----------------
__global__ void cvt_wt(const float* __restrict__ W, __nv_bfloat16* __restrict__ hi,
                       __nv_bfloat16* __restrict__ lo, int K, int N) {
    const int i = blockIdx.x * blockDim.x + threadIdx.x;
    if (i >= K * N) return;
    const int n = i / K, k = i % K;
    const float v = W[k * N + n];
    const __nv_bfloat16 h = __float2bfloat16(v);
    hi[i] = h;
    lo[i] = __float2bfloat16(v - __bfloat162float(h));
}
__global__ void cvt_wt_gat(const float* __restrict__ W, __nv_bfloat16* __restrict__ hi,
                           __nv_bfloat16* __restrict__ lo) {
    const int i = blockIdx.x * blockDim.x + threadIdx.x;
    if (i >= 6 * 65536) return;
    const int pl = i >> 16, r = i & 65535;
    const int n = r / 256, k = r % 256;
    const float v = W[(size_t)pl * 65536 + k * 256 + n];
    const __nv_bfloat16 h = __float2bfloat16(v);
    hi[i] = h;
    lo[i] = __float2bfloat16(v - __bfloat162float(h));
}
__global__ void cvt_split(const float* __restrict__ in, __nv_bfloat16* __restrict__ hi,
                          __nv_bfloat16* __restrict__ lo, int n) {
    const int i = blockIdx.x * blockDim.x + threadIdx.x;
    if (i >= n) return;
    const float v = in[i];
    const __nv_bfloat16 h = __float2bfloat16(v);
    hi[i] = h;
    lo[i] = __float2bfloat16(v - __bfloat162float(h));
}

// ---------------- one-time zero init: agg + ssrc + sdst + denom ----------------
__global__ void init_layer(float* __restrict__ agg, float* __restrict__ ssrc,
                           float* __restrict__ sdst, float* __restrict__ denom) {
    const int i = blockIdx.x * blockDim.x + threadIdx.x;   // NN*64 threads (float4)
    if (i >= NN * 64) return;
    ((float4*)agg)[i] = make_float4(0.f, 0.f, 0.f, 0.f);
    if (i < NN * 2) {
        ((float4*)ssrc)[i]  = make_float4(0.f, 0.f, 0.f, 0.f);
        ((float4*)sdst)[i]  = make_float4(0.f, 0.f, 0.f, 0.f);
        ((float4*)denom)[i] = make_float4(0.f, 0.f, 0.f, 0.f);
    }
}

// ---------------- fused edge pass: fp16 gather (head-major, coalesced) ----------------
// One warp per REAL edge (self-loops handled in finalize).
__global__ void edge_fused(const int* __restrict__ src, const int* __restrict__ dst,
                           const float* __restrict__ s_src, const float* __restrict__ s_dst,
                           const __half* __restrict__ hp16,
                           float* __restrict__ denom, float* __restrict__ agg) {
    const int gw = (blockIdx.x * blockDim.x + threadIdx.x) >> 5;
    const int lane = threadIdx.x & 31;
    if (gw >= EE) return;
    const int s = __ldg(&src[gw]);
    const int d = __ldg(&dst[gw]);
    float ex = 0.f;
    if (lane < 8) {
        const float zz = __ldg(&s_src[s * NH + lane]) + __ldg(&s_dst[d * NH + lane]);
        const float e = zz > 0.f ? zz : 0.2f * zz;
        ex = __expf(e);
        atomicAdd(&denom[d * NH + lane], ex);
    }
    float a[8];
#pragma unroll
    for (int h = 0; h < 8; h++) a[h] = __shfl_sync(0xffffffffu, ex, h);
    const __half* rowp = hp16 + (size_t)s * 256;
    float* aggp = agg + (size_t)d * 256;
#pragma unroll
    for (int h = 0; h < 8; h++) {
        const int j = h * 32 + lane;
        atomicAdd(&aggp[j], a[h] * __half2float(__ldg(&rowp[j])));
    }
}

// ---------------- finalize: self-loop + normalize + bias + ELU + zero for next layer ----
__global__ void finalize_elu(float* __restrict__ agg, float* __restrict__ denom,
                             float* __restrict__ ssrc, float* __restrict__ sdst,
                             const __half* __restrict__ hp16,
                             const float* __restrict__ b,
                             float* __restrict__ outf,
                             __nv_bfloat16* __restrict__ ohi,
                             __nv_bfloat16* __restrict__ olo,
                             int rowStride) {
    const int n = blockIdx.x;
    const int t = threadIdx.x;
    const int h = t >> 5;
    // self-loop contribution (same fp16-quantized hp as edge path)
    const float zz = ssrc[n * NH + h] + sdst[n * NH + h];
    const float le = zz > 0.f ? zz : 0.2f * zz;
    const float exs = __expf(le);
    const float hpv = __half2float(hp16[n * 256 + t]);
    float v = (agg[n * 256 + t] + exs * hpv) / (denom[n * NH + h] + exs) + b[t];
    v = v > 0.f ? v : expm1f(v);
    const size_t o = (size_t)n * rowStride + t;
    if (outf) outf[o] = v;
    const __nv_bfloat16 hh = __float2bfloat16(v);
    ohi[o] = hh;
    olo[o] = __float2bfloat16(v - __bfloat162float(hh));
    // zero this node's accumulators for the next layer
    __syncthreads();
    agg[n * 256 + t] = 0.f;
    if (t < NH) {
        ssrc[n * NH + t]  = 0.f;
        sdst[n * NH + t]  = 0.f;
        denom[n * NH + t] = 0.f;
    }
}

// ---------------- semantic attention; emit z as bf16 hi/lo ----------------
__global__ void sem_kernel(const float* __restrict__ hid, const float* __restrict__ W2,
                           const float* __restrict__ emb,
                           __nv_bfloat16* __restrict__ zhi,
                           __nv_bfloat16* __restrict__ zlo) {
    const int warp = (blockIdx.x * blockDim.x + threadIdx.x) >> 5;
    const int lane = threadIdx.x & 31;
    if (warp >= NN) return;
    float sc[3];
#pragma unroll
    for (int p = 0; p < 3; p++) {
        float part = 0.f;
#pragma unroll
        for (int t = lane; t < 128; t += 32)
            part += hid[(size_t)(warp * 3 + p) * 128 + t] * W2[t];
#pragma unroll
        for (int o = 16; o > 0; o >>= 1) part += __shfl_down_sync(0xffffffffu, part, o);
        sc[p] = __shfl_sync(0xffffffffu, part, 0);
    }
    const float mx = fmaxf(sc[0], fmaxf(sc[1], sc[2]));
    const float e0 = __expf(sc[0] - mx), e1 = __expf(sc[1] - mx), e2 = __expf(sc[2] - mx);
    const float inv = 1.f / (e0 + e1 + e2);
    const float w0 = e0 * inv, w1 = e1 * inv, w2 = e2 * inv;
    const float* er = &emb[(size_t)warp * 768];
#pragma unroll
    for (int j = lane; j < 256; j += 32) {
        const float v = w0 * er[j] + w1 * er[256 + j] + w2 * er[512 + j];
        const __nv_bfloat16 h = __float2bfloat16(v);
        zhi[(size_t)warp * 256 + j] = h;
        zlo[(size_t)warp * 256 + j] = __float2bfloat16(v - __bfloat162float(h));
    }
}

// ---------------- classifier head ----------------
__global__ void cls_final(const float* __restrict__ hcls, const float* __restrict__ W2,
                          const float* __restrict__ b2, float* __restrict__ out) {
    const int warp = (blockIdx.x * blockDim.x + threadIdx.x) >> 5;
    const int lane = threadIdx.x & 31;
    if (warp >= NN) return;
    float p0 = 0.f, p1 = 0.f;
#pragma unroll
    for (int t = lane; t < 128; t += 32) {
        const float v = hcls[(size_t)warp * 128 + t];
        p0 += v * W2[t * 2 + 0];
        p1 += v * W2[t * 2 + 1];
    }
#pragma unroll
    for (int o = 16; o > 0; o >>= 1) {
        p0 += __shfl_down_sync(0xffffffffu, p0, o);
        p1 += __shfl_down_sync(0xffffffffu, p1, o);
    }
    if (lane == 0) {
        out[(size_t)warp * 2 + 0] = p0 + b2[0];
        out[(size_t)warp * 2 + 1] = p1 + b2[1];
    }
}

extern "C" void kernel_launch(void* const* d_in, const int* in_sizes, int n_in,
                              void* d_out, int out_size) {
    const float* x        = (const float*)d_in[0];
    const int*   edges    = (const int*)  d_in[1];
    const float* proj_W   = (const float*)d_in[2];
    const float* proj_b   = (const float*)d_in[3];
    const float* gat_W    = (const float*)d_in[4];
    const float* gat_asrc = (const float*)d_in[5];
    const float* gat_adst = (const float*)d_in[6];
    const float* gat_b    = (const float*)d_in[7];
    const float* sem_W1   = (const float*)d_in[8];
    const float* sem_b1   = (const float*)d_in[9];
    const float* sem_W2   = (const float*)d_in[10];
    const float* cls_W1   = (const float*)d_in[11];
    const float* cls_b1   = (const float*)d_in[12];
    const float* cls_W2   = (const float*)d_in[13];
    const float* cls_b2   = (const float*)d_in[14];
    float* out = (float*)d_out;

    float *agg, *ssrc, *sdst, *denom, *emb, *hid, *hcls;
    __half* hp16;
    __nv_bfloat16 *xhi, *xlo, *h0hi, *h0lo, *hhi, *hlo, *ehi, *elo, *zhi, *zlo, *whi, *wlo;
    cudaGetSymbolAddress((void**)&agg,   g_agg);
    cudaGetSymbolAddress((void**)&ssrc,  g_ssrc);
    cudaGetSymbolAddress((void**)&sdst,  g_sdst);
    cudaGetSymbolAddress((void**)&denom, g_denom);
    cudaGetSymbolAddress((void**)&emb,   g_emb);
    cudaGetSymbolAddress((void**)&hid,   g_hid);
    cudaGetSymbolAddress((void**)&hcls,  g_hcls);
    cudaGetSymbolAddress((void**)&hp16,  g_hp16);
    cudaGetSymbolAddress((void**)&xhi,   g_xhi);
    cudaGetSymbolAddress((void**)&xlo,   g_xlo);
    cudaGetSymbolAddress((void**)&h0hi,  g_h0hi);
    cudaGetSymbolAddress((void**)&h0lo,  g_h0lo);
    cudaGetSymbolAddress((void**)&hhi,   g_hhi);
    cudaGetSymbolAddress((void**)&hlo,   g_hlo);
    cudaGetSymbolAddress((void**)&ehi,   g_ehi);
    cudaGetSymbolAddress((void**)&elo,   g_elo);
    cudaGetSymbolAddress((void**)&zhi,   g_zhi);
    cudaGetSymbolAddress((void**)&zlo,   g_zlo);
    cudaGetSymbolAddress((void**)&whi,   g_whi);
    cudaGetSymbolAddress((void**)&wlo,   g_wlo);

    cudaFuncSetAttribute(gemm_mma<1, 0>, cudaFuncAttributeMaxDynamicSharedMemorySize, SMEMSZ);
    cudaFuncSetAttribute(gemm_mma<2, 0>, cudaFuncAttributeMaxDynamicSharedMemorySize, SMEMSZ);
    cudaFuncSetAttribute(gemm_mma<0, 1>, cudaFuncAttributeMaxDynamicSharedMemorySize, SMEMSZ);
    cudaFuncSetAttribute(gemm_mma<0, 2>, cudaFuncAttributeMaxDynamicSharedMemorySize, SMEMSZ);

    const int OFF_PROJ = 0;
    const int OFF_GAT  = 32768;
    const int OFF_SEM  = 32768 + 6 * 65536;
    const int OFF_CLS  = OFF_SEM + 32768;

    cvt_wt<<<(128 * 256 + 255) / 256, 256>>>(proj_W, whi + OFF_PROJ, wlo + OFF_PROJ, 128, 256);
    cvt_wt_gat<<<(6 * 65536 + 255) / 256, 256>>>(gat_W, whi + OFF_GAT, wlo + OFF_GAT);
    cvt_wt<<<(256 * 128 + 255) / 256, 256>>>(sem_W1, whi + OFF_SEM, wlo + OFF_SEM, 256, 128);
    cvt_wt<<<(256 * 128 + 255) / 256, 256>>>(cls_W1, whi + OFF_CLS, wlo + OFF_CLS, 256, 128);

    cvt_split<<<(NN * 128 + 255) / 256, 256>>>(x, xhi, xlo, NN * 128);
    init_layer<<<(NN * 64 + 255) / 256, 256>>>(agg, ssrc, sdst, denom);

    const int aggrBlocks = (EE * 32) / 256;            // 100000
    const int warpNodeBlocks = (NN * 32 + 255) / 256;  // 6250
    const dim3 gProj(2, (NN + 127) / 128);
    const dim3 gGat(2, (NN + 127) / 128);
    const dim3 gSem(1, (3 * NN + 127) / 128);
    const dim3 gCls(1, (NN + 127) / 128);

    // proj: h0(hi/lo) = x @ proj_W + proj_b
    gemm_mma<1, 0><<<gProj, 256, SMEMSZ>>>(xhi, xlo, whi + OFF_PROJ, wlo + OFF_PROJ,
                                           proj_b, nullptr, h0hi, h0lo,
                                           nullptr, nullptr, nullptr, nullptr, nullptr,
                                           NN, 128, 256);

    for (int p = 0; p < 3; p++) {
        const int* srcp = edges + (size_t)p * 2 * EE;
        const int* dstp = srcp + EE;
        for (int l = 0; l < 2; l++) {
            const int pl = p * 2 + l;
            const __nv_bfloat16* Ah = (l == 0) ? h0hi : hhi;
            const __nv_bfloat16* Al = (l == 0) ? h0lo : hlo;
            gemm_mma<2, 0><<<gGat, 256, SMEMSZ>>>(
                Ah, Al, whi + OFF_GAT + pl * 65536, wlo + OFF_GAT + pl * 65536,
                nullptr, nullptr, nullptr, nullptr,
                hp16, gat_asrc + pl * 256, gat_adst + pl * 256, ssrc, sdst,
                NN, 256, 256);
            edge_fused<<<aggrBlocks, 256>>>(srcp, dstp, ssrc, sdst, hp16, denom, agg);
            if (l == 0) {
                finalize_elu<<<NN, 256>>>(agg, denom, ssrc, sdst, hp16,
                                          gat_b + pl * 256, nullptr, hhi, hlo, 256);
            } else {
                finalize_elu<<<NN, 256>>>(agg, denom, ssrc, sdst, hp16,
                                          gat_b + pl * 256,
                                          emb + p * 256, ehi + p * 256, elo + p * 256, 768);
            }
        }
    }

    // semantic attention
    gemm_mma<0, 1><<<gSem, 256, SMEMSZ>>>(ehi, elo, whi + OFF_SEM, wlo + OFF_SEM,
                                          sem_b1, hid, nullptr, nullptr,
                                          nullptr, nullptr, nullptr, nullptr, nullptr,
                                          3 * NN, 256, 128);
    sem_kernel<<<warpNodeBlocks, 256>>>(hid, sem_W2, emb, zhi, zlo);

    // classifier
    gemm_mma<0, 2><<<gCls, 256, SMEMSZ>>>(zhi, zlo, whi + OFF_CLS, wlo + OFF_CLS,
                                          cls_b1, hcls, nullptr, nullptr,
                                          nullptr, nullptr, nullptr, nullptr, nullptr,
                                          NN, 256, 128);
    cls_final<<<warpNodeBlocks, 256>>>(hcls, cls_W2, cls_b2, out);
}

// round 15
// speedup vs baseline: 1.0240x; 1.0240x over previous
#include <cuda_runtime.h>
#include <cuda_bf16.h>
#include <cuda_fp16.h>
#include <math.h>
#include <cstdint>

#define NN 50000
#define EE 800000
#define NH 8

// ---------------- scratch (device globals; per-metapath where needed) ----------------
__device__ __align__(16) float g_agg  [3][NN * 256];
__device__ __align__(16) float g_ssrc [3][NN * NH];
__device__ __align__(16) float g_sdst [3][NN * NH];
__device__ __align__(16) float g_denom[3][NN * NH];
__device__ float g_emb  [NN * 3 * 256];
__device__ float g_hid  [NN * 3 * 128];
__device__ float g_hcls [NN * 128];

__device__ __align__(16) __half g_hp16[3][NN * 256];

__device__ __align__(16) __nv_bfloat16 g_xhi [NN * 128];
__device__ __align__(16) __nv_bfloat16 g_xlo [NN * 128];
__device__ __align__(16) __nv_bfloat16 g_h0hi[NN * 256];
__device__ __align__(16) __nv_bfloat16 g_h0lo[NN * 256];
__device__ __align__(16) __nv_bfloat16 g_hhi [3][NN * 256];
__device__ __align__(16) __nv_bfloat16 g_hlo [3][NN * 256];
__device__ __align__(16) __nv_bfloat16 g_ehi [NN * 3 * 256];
__device__ __align__(16) __nv_bfloat16 g_elo [NN * 3 * 256];
__device__ __align__(16) __nv_bfloat16 g_zhi [NN * 256];
__device__ __align__(16) __nv_bfloat16 g_zlo [NN * 256];
// transposed+split weights [N][K]
__device__ __align__(16) __nv_bfloat16 g_whi [491520];
__device__ __align__(16) __nv_bfloat16 g_wlo [491520];

// ---------------- warp-MMA + cp.async helpers (plain sm_80+ PTX) ----------------
__device__ __forceinline__ uint32_t smem_u32(const void* p) {
    uint32_t a;
    asm("{ .reg .u64 t; cvta.to.shared.u64 t, %1; cvt.u32.u64 %0, t; }" : "=r"(a) : "l"(p));
    return a;
}
__device__ __forceinline__ void ldsm_x4(uint32_t* r, uint32_t addr) {
    asm volatile("ldmatrix.sync.aligned.m8n8.x4.shared.b16 {%0,%1,%2,%3}, [%4];"
                 : "=r"(r[0]), "=r"(r[1]), "=r"(r[2]), "=r"(r[3]) : "r"(addr));
}
__device__ __forceinline__ void ldsm_x2(uint32_t* r, uint32_t addr) {
    asm volatile("ldmatrix.sync.aligned.m8n8.x2.shared.b16 {%0,%1}, [%2];"
                 : "=r"(r[0]), "=r"(r[1]) : "r"(addr));
}
__device__ __forceinline__ void mma_bf16(float* c, const uint32_t* a, const uint32_t* b) {
    asm volatile("mma.sync.aligned.m16n8k16.row.col.f32.bf16.bf16.f32 "
                 "{%0,%1,%2,%3}, {%4,%5,%6,%7}, {%8,%9}, {%0,%1,%2,%3};"
                 : "+f"(c[0]), "+f"(c[1]), "+f"(c[2]), "+f"(c[3])
                 : "r"(a[0]), "r"(a[1]), "r"(a[2]), "r"(a[3]), "r"(b[0]), "r"(b[1]));
}
__device__ __forceinline__ void cp16(uint32_t saddr, const void* g, int srcsize) {
    asm volatile("cp.async.cg.shared.global [%0], [%1], 16, %2;"
                 :: "r"(saddr), "l"(g), "r"(srcsize) : "memory");
}
#define CP_COMMIT() asm volatile("cp.async.commit_group;" ::: "memory")
#define CP_WAIT(n)  asm volatile("cp.async.wait_group %0;" :: "n"(n) : "memory")

// ---------------- bf16-split tensor GEMM, cp.async double-buffered ----------------
#define LDSE   40
#define PLANE  10240
#define BUFSZ  20480
#define BHALF  40960
#define SMEMSZ 81920
template <int EPI, int ACT>   // EPI: 0 fp32 C, 1 split bf16 C, 2 GAT. ACT: 0/1 tanh/2 relu
__global__ void __launch_bounds__(256, 1)
gemm_mma(const __nv_bfloat16* __restrict__ Ahi, const __nv_bfloat16* __restrict__ Alo,
         const __nv_bfloat16* __restrict__ Bhi, const __nv_bfloat16* __restrict__ Blo,
         const float* __restrict__ bias,
         float* __restrict__ C, __nv_bfloat16* __restrict__ Chi,
         __nv_bfloat16* __restrict__ Clo,
         __half* __restrict__ H16,
         const float* __restrict__ asrc, const float* __restrict__ adst,
         float* __restrict__ Ssrc, float* __restrict__ Sdst,
         int M, int K, int Nc) {
    extern __shared__ __align__(16) char smem[];
    const uint32_t sAu = smem_u32(smem);
    const uint32_t sBu = sAu + BHALF;
    const int tid = threadIdx.x;
    const int lane = tid & 31;
    const int w = tid >> 5;
    const int wm = w & 3, wn = w >> 2;
    const int rowBase = blockIdx.y * 128;
    const int colBase = blockIdx.x * 128;

    float acc[2][8][4];
#pragma unroll
    for (int i = 0; i < 2; i++)
#pragma unroll
        for (int j = 0; j < 8; j++)
#pragma unroll
            for (int e = 0; e < 4; e++) acc[i][j][e] = 0.f;

    auto load_tile = [&](int buf, int k0) {
#pragma unroll
        for (int t = 0; t < 2; t++) {
            const int idx = tid + t * 256;
            const int row = idx >> 2;
            const int cb  = (idx & 3) * 16;
            const uint32_t soff = (uint32_t)(row * (LDSE * 2) + cb);
            const int grow = rowBase + row;
            const int ar = grow < M ? grow : (M - 1);
            const int ssz = grow < M ? 16 : 0;
            const char* gah = (const char*)Ahi + ((size_t)ar * K + k0) * 2 + cb;
            const char* gal = (const char*)Alo + ((size_t)ar * K + k0) * 2 + cb;
            cp16(sAu + buf * BUFSZ + soff,          gah, ssz);
            cp16(sAu + buf * BUFSZ + PLANE + soff,  gal, ssz);
            const int gn = colBase + row;
            const char* gbh = (const char*)Bhi + ((size_t)gn * K + k0) * 2 + cb;
            const char* gbl = (const char*)Blo + ((size_t)gn * K + k0) * 2 + cb;
            cp16(sBu + buf * BUFSZ + soff,          gbh, 16);
            cp16(sBu + buf * BUFSZ + PLANE + soff,  gbl, 16);
        }
    };

    const int ntiles = K >> 5;
    load_tile(0, 0);
    CP_COMMIT();

    for (int c = 0; c < ntiles; c++) {
        const int cur = c & 1;
        if (c + 1 < ntiles) {
            load_tile(cur ^ 1, (c + 1) << 5);
            CP_COMMIT();
            CP_WAIT(1);
        } else {
            CP_WAIT(0);
        }
        __syncthreads();

        const uint32_t aB = sAu + cur * BUFSZ;
        const uint32_t bB = sBu + cur * BUFSZ;
#pragma unroll
        for (int k16 = 0; k16 < 2; k16++) {
            uint32_t ahi[2][4], alo[2][4];
#pragma unroll
            for (int mt = 0; mt < 2; mt++) {
                const uint32_t ra = aB +
                    (uint32_t)((wm * 32 + mt * 16 + (lane & 15)) * (LDSE * 2)
                               + k16 * 32 + (lane >> 4) * 16);
                ldsm_x4(ahi[mt], ra);
                ldsm_x4(alo[mt], ra + PLANE);
            }
#pragma unroll
            for (int nt = 0; nt < 8; nt++) {
                const uint32_t rb = bB +
                    (uint32_t)((wn * 64 + nt * 8 + (lane & 7)) * (LDSE * 2)
                               + k16 * 32 + ((lane >> 3) & 1) * 16);
                uint32_t bhi[2], blo[2];
                ldsm_x2(bhi, rb);
                ldsm_x2(blo, rb + PLANE);
#pragma unroll
                for (int mt = 0; mt < 2; mt++) {
                    mma_bf16(acc[mt][nt], ahi[mt], bhi);
                    mma_bf16(acc[mt][nt], ahi[mt], blo);
                    mma_bf16(acc[mt][nt], alo[mt], bhi);
                }
            }
        }
        __syncthreads();
    }

    const int g = lane >> 2, tq = lane & 3;
    if (EPI == 2) {
        const int headbase = blockIdx.x * 4 + wn * 2;
#pragma unroll
        for (int mt = 0; mt < 2; mt++) {
#pragma unroll
            for (int half = 0; half < 2; half++) {
                const int row = rowBase + wm * 32 + mt * 16 + g + half * 8;
                float ps0 = 0.f, ps1 = 0.f, pd0 = 0.f, pd1 = 0.f;
                if (row < M) {
#pragma unroll
                    for (int nt = 0; nt < 8; nt++) {
                        const int col = colBase + wn * 64 + nt * 8 + tq * 2;
                        const float v0 = acc[mt][nt][half * 2 + 0];
                        const float v1 = acc[mt][nt][half * 2 + 1];
                        *(__half2*)(H16 + (size_t)row * 256 + col) =
                            __floats2half2_rn(v0, v1);
                        const float a0s = __ldg(&asrc[col]), a1s = __ldg(&asrc[col + 1]);
                        const float a0d = __ldg(&adst[col]), a1d = __ldg(&adst[col + 1]);
                        if (nt < 4) { ps0 += v0 * a0s + v1 * a1s; pd0 += v0 * a0d + v1 * a1d; }
                        else        { ps1 += v0 * a0s + v1 * a1s; pd1 += v0 * a0d + v1 * a1d; }
                    }
                }
                ps0 += __shfl_down_sync(0xffffffffu, ps0, 2);
                ps0 += __shfl_down_sync(0xffffffffu, ps0, 1);
                ps1 += __shfl_down_sync(0xffffffffu, ps1, 2);
                ps1 += __shfl_down_sync(0xffffffffu, ps1, 1);
                pd0 += __shfl_down_sync(0xffffffffu, pd0, 2);
                pd0 += __shfl_down_sync(0xffffffffu, pd0, 1);
                pd1 += __shfl_down_sync(0xffffffffu, pd1, 2);
                pd1 += __shfl_down_sync(0xffffffffu, pd1, 1);
                if (tq == 0 && row < M) {
                    atomicAdd(&Ssrc[row * NH + headbase + 0], ps0);
                    atomicAdd(&Ssrc[row * NH + headbase + 1], ps1);
                    atomicAdd(&Sdst[row * NH + headbase + 0], pd0);
                    atomicAdd(&Sdst[row * NH + headbase + 1], pd1);
                }
            }
        }
    } else {
#pragma unroll
        for (int mt = 0; mt < 2; mt++) {
#pragma unroll
            for (int nt = 0; nt < 8; nt++) {
                const int col = colBase + wn * 64 + nt * 8 + tq * 2;
#pragma unroll
                for (int half = 0; half < 2; half++) {
                    const int row = rowBase + wm * 32 + mt * 16 + g + half * 8;
                    if (row < M) {
#pragma unroll
                        for (int e = 0; e < 2; e++) {
                            float v = acc[mt][nt][half * 2 + e];
                            const int c = col + e;
                            if (bias) v += bias[c];
                            if (ACT == 1) v = tanhf(v);
                            else if (ACT == 2) v = fmaxf(v, 0.f);
                            const size_t o = (size_t)row * Nc + c;
                            if (EPI == 1) {
                                const __nv_bfloat16 h = __float2bfloat16(v);
                                Chi[o] = h;
                                Clo[o] = __float2bfloat16(v - __bfloat162float(h));
                            } else {
                                C[o] = v;
                            }
                        }
                    }
                }
            }
        }
    }
}

// ---------------- weight transpose + split ----------------
__global__ void cvt_wt(const float* __restrict__ W, __nv_bfloat16* __restrict__ hi,
                       __nv_bfloat16* __restrict__ lo, int K, int N) {
    const int i = blockIdx.x * blockDim.x + threadIdx.x;
    if (i >= K * N) return;
    const int n = i / K, k = i % K;
    const float v = W[k * N + n];
    const __nv_bfloat16 h = __float2bfloat16(v);
    hi[i] = h;
    lo[i] = __float2bfloat16(v - __bfloat162float(h));
}
__global__ void cvt_wt_gat(const float* __restrict__ W, __nv_bfloat16* __restrict__ hi,
                           __nv_bfloat16* __restrict__ lo) {
    const int i = blockIdx.x * blockDim.x + threadIdx.x;
    if (i >= 6 * 65536) return;
    const int pl = i >> 16, r = i & 65535;
    const int n = r / 256, k = r % 256;
    const float v = W[(size_t)pl * 65536 + k * 256 + n];
    const __nv_bfloat16 h = __float2bfloat16(v);
    hi[i] = h;
    lo[i] = __float2bfloat16(v - __bfloat162float(h));
}
__global__ void cvt_split(const float* __restrict__ in, __nv_bfloat16* __restrict__ hi,
                          __nv_bfloat16* __restrict__ lo, int n) {
    const int i = blockIdx.x * blockDim.x + threadIdx.x;
    if (i >= n) return;
    const float v = in[i];
    const __nv_bfloat16 h = __float2bfloat16(v);
    hi[i] = h;
    lo[i] = __float2bfloat16(v - __bfloat162float(h));
}

// ---------------- zero init for one metapath's accumulators ----------------
__global__ void init_layer(float* __restrict__ agg, float* __restrict__ ssrc,
                           float* __restrict__ sdst, float* __restrict__ denom) {
    const int i = blockIdx.x * blockDim.x + threadIdx.x;   // NN*64 (float4)
    if (i >= NN * 64) return;
    ((float4*)agg)[i] = make_float4(0.f, 0.f, 0.f, 0.f);
    if (i < NN * 2) {
        ((float4*)ssrc)[i]  = make_float4(0.f, 0.f, 0.f, 0.f);
        ((float4*)sdst)[i]  = make_float4(0.f, 0.f, 0.f, 0.f);
        ((float4*)denom)[i] = make_float4(0.f, 0.f, 0.f, 0.f);
    }
}

// ---------------- fused edge pass: fp16 gather (head-major, coalesced) ----------------
__global__ void edge_fused(const int* __restrict__ src, const int* __restrict__ dst,
                           const float* __restrict__ s_src, const float* __restrict__ s_dst,
                           const __half* __restrict__ hp16,
                           float* __restrict__ denom, float* __restrict__ agg) {
    const int gw = (blockIdx.x * blockDim.x + threadIdx.x) >> 5;
    const int lane = threadIdx.x & 31;
    if (gw >= EE) return;
    const int s = __ldg(&src[gw]);
    const int d = __ldg(&dst[gw]);
    float ex = 0.f;
    if (lane < 8) {
        const float zz = __ldg(&s_src[s * NH + lane]) + __ldg(&s_dst[d * NH + lane]);
        const float e = zz > 0.f ? zz : 0.2f * zz;
        ex = __expf(e);
        atomicAdd(&denom[d * NH + lane], ex);
    }
    float a[8];
#pragma unroll
    for (int h = 0; h < 8; h++) a[h] = __shfl_sync(0xffffffffu, ex, h);
    const __half* rowp = hp16 + (size_t)s * 256;
    float* aggp = agg + (size_t)d * 256;
#pragma unroll
    for (int h = 0; h < 8; h++) {
        const int j = h * 32 + lane;
        atomicAdd(&aggp[j], a[h] * __half2float(__ldg(&rowp[j])));
    }
}

// ---------------- finalize: self-loop + normalize + bias + ELU + zero for next layer ----
__global__ void finalize_elu(float* __restrict__ agg, float* __restrict__ denom,
                             float* __restrict__ ssrc, float* __restrict__ sdst,
                             const __half* __restrict__ hp16,
                             const float* __restrict__ b,
                             float* __restrict__ outf,
                             __nv_bfloat16* __restrict__ ohi,
                             __nv_bfloat16* __restrict__ olo,
                             int rowStride) {
    const int n = blockIdx.x;
    const int t = threadIdx.x;
    const int h = t >> 5;
    const float zz = ssrc[n * NH + h] + sdst[n * NH + h];
    const float le = zz > 0.f ? zz : 0.2f * zz;
    const float exs = __expf(le);
    const float hpv = __half2float(hp16[n * 256 + t]);
    float v = (agg[n * 256 + t] + exs * hpv) / (denom[n * NH + h] + exs) + b[t];
    v = v > 0.f ? v : expm1f(v);
    const size_t o = (size_t)n * rowStride + t;
    if (outf) outf[o] = v;
    const __nv_bfloat16 hh = __float2bfloat16(v);
    ohi[o] = hh;
    olo[o] = __float2bfloat16(v - __bfloat162float(hh));
    __syncthreads();
    agg[n * 256 + t] = 0.f;
    if (t < NH) {
        ssrc[n * NH + t]  = 0.f;
        sdst[n * NH + t]  = 0.f;
        denom[n * NH + t] = 0.f;
    }
}

// ---------------- semantic attention; emit z as bf16 hi/lo ----------------
__global__ void sem_kernel(const float* __restrict__ hid, const float* __restrict__ W2,
                           const float* __restrict__ emb,
                           __nv_bfloat16* __restrict__ zhi,
                           __nv_bfloat16* __restrict__ zlo) {
    const int warp = (blockIdx.x * blockDim.x + threadIdx.x) >> 5;
    const int lane = threadIdx.x & 31;
    if (warp >= NN) return;
    float sc[3];
#pragma unroll
    for (int p = 0; p < 3; p++) {
        float part = 0.f;
#pragma unroll
        for (int t = lane; t < 128; t += 32)
            part += hid[(size_t)(warp * 3 + p) * 128 + t] * W2[t];
#pragma unroll
        for (int o = 16; o > 0; o >>= 1) part += __shfl_down_sync(0xffffffffu, part, o);
        sc[p] = __shfl_sync(0xffffffffu, part, 0);
    }
    const float mx = fmaxf(sc[0], fmaxf(sc[1], sc[2]));
    const float e0 = __expf(sc[0] - mx), e1 = __expf(sc[1] - mx), e2 = __expf(sc[2] - mx);
    const float inv = 1.f / (e0 + e1 + e2);
    const float w0 = e0 * inv, w1 = e1 * inv, w2 = e2 * inv;
    const float* er = &emb[(size_t)warp * 768];
#pragma unroll
    for (int j = lane; j < 256; j += 32) {
        const float v = w0 * er[j] + w1 * er[256 + j] + w2 * er[512 + j];
        const __nv_bfloat16 h = __float2bfloat16(v);
        zhi[(size_t)warp * 256 + j] = h;
        zlo[(size_t)warp * 256 + j] = __float2bfloat16(v - __bfloat162float(h));
    }
}

// ---------------- classifier head ----------------
__global__ void cls_final(const float* __restrict__ hcls, const float* __restrict__ W2,
                          const float* __restrict__ b2, float* __restrict__ out) {
    const int warp = (blockIdx.x * blockDim.x + threadIdx.x) >> 5;
    const int lane = threadIdx.x & 31;
    if (warp >= NN) return;
    float p0 = 0.f, p1 = 0.f;
#pragma unroll
    for (int t = lane; t < 128; t += 32) {
        const float v = hcls[(size_t)warp * 128 + t];
        p0 += v * W2[t * 2 + 0];
        p1 += v * W2[t * 2 + 1];
    }
#pragma unroll
    for (int o = 16; o > 0; o >>= 1) {
        p0 += __shfl_down_sync(0xffffffffu, p0, o);
        p1 += __shfl_down_sync(0xffffffffu, p1, o);
    }
    if (lane == 0) {
        out[(size_t)warp * 2 + 0] = p0 + b2[0];
        out[(size_t)warp * 2 + 1] = p1 + b2[1];
    }
}

extern "C" void kernel_launch(void* const* d_in, const int* in_sizes, int n_in,
                              void* d_out, int out_size) {
    const float* x        = (const float*)d_in[0];
    const int*   edges    = (const int*)  d_in[1];
    const float* proj_W   = (const float*)d_in[2];
    const float* proj_b   = (const float*)d_in[3];
    const float* gat_W    = (const float*)d_in[4];
    const float* gat_asrc = (const float*)d_in[5];
    const float* gat_adst = (const float*)d_in[6];
    const float* gat_b    = (const float*)d_in[7];
    const float* sem_W1   = (const float*)d_in[8];
    const float* sem_b1   = (const float*)d_in[9];
    const float* sem_W2   = (const float*)d_in[10];
    const float* cls_W1   = (const float*)d_in[11];
    const float* cls_b1   = (const float*)d_in[12];
    const float* cls_W2   = (const float*)d_in[13];
    const float* cls_b2   = (const float*)d_in[14];
    float* out = (float*)d_out;

    float *aggB, *ssrcB, *sdstB, *denomB, *emb, *hid, *hcls;
    __half* hp16B;
    __nv_bfloat16 *xhi, *xlo, *h0hi, *h0lo, *hhiB, *hloB, *ehi, *elo, *zhi, *zlo, *whi, *wlo;
    cudaGetSymbolAddress((void**)&aggB,  g_agg);
    cudaGetSymbolAddress((void**)&ssrcB, g_ssrc);
    cudaGetSymbolAddress((void**)&sdstB, g_sdst);
    cudaGetSymbolAddress((void**)&denomB,g_denom);
    cudaGetSymbolAddress((void**)&emb,   g_emb);
    cudaGetSymbolAddress((void**)&hid,   g_hid);
    cudaGetSymbolAddress((void**)&hcls,  g_hcls);
    cudaGetSymbolAddress((void**)&hp16B, g_hp16);
    cudaGetSymbolAddress((void**)&xhi,   g_xhi);
    cudaGetSymbolAddress((void**)&xlo,   g_xlo);
    cudaGetSymbolAddress((void**)&h0hi,  g_h0hi);
    cudaGetSymbolAddress((void**)&h0lo,  g_h0lo);
    cudaGetSymbolAddress((void**)&hhiB,  g_hhi);
    cudaGetSymbolAddress((void**)&hloB,  g_hlo);
    cudaGetSymbolAddress((void**)&ehi,   g_ehi);
    cudaGetSymbolAddress((void**)&elo,   g_elo);
    cudaGetSymbolAddress((void**)&zhi,   g_zhi);
    cudaGetSymbolAddress((void**)&zlo,   g_zlo);
    cudaGetSymbolAddress((void**)&whi,   g_whi);
    cudaGetSymbolAddress((void**)&wlo,   g_wlo);

    cudaFuncSetAttribute(gemm_mma<1, 0>, cudaFuncAttributeMaxDynamicSharedMemorySize, SMEMSZ);
    cudaFuncSetAttribute(gemm_mma<2, 0>, cudaFuncAttributeMaxDynamicSharedMemorySize, SMEMSZ);
    cudaFuncSetAttribute(gemm_mma<0, 1>, cudaFuncAttributeMaxDynamicSharedMemorySize, SMEMSZ);
    cudaFuncSetAttribute(gemm_mma<0, 2>, cudaFuncAttributeMaxDynamicSharedMemorySize, SMEMSZ);

    // persistent streams/events for the 3 metapath chains (created once; no device mem)
    static cudaStream_t st[3] = {nullptr, nullptr, nullptr};
    static cudaEvent_t evFork = nullptr, evJoin[3] = {nullptr, nullptr, nullptr};
    if (!st[0]) {
        for (int p = 0; p < 3; p++) {
            cudaStreamCreateWithFlags(&st[p], cudaStreamNonBlocking);
            cudaEventCreateWithFlags(&evJoin[p], cudaEventDisableTiming);
        }
        cudaEventCreateWithFlags(&evFork, cudaEventDisableTiming);
    }

    const int OFF_PROJ = 0;
    const int OFF_GAT  = 32768;
    const int OFF_SEM  = 32768 + 6 * 65536;
    const int OFF_CLS  = OFF_SEM + 32768;

    // ---- prologue on capture-origin (default) stream ----
    cvt_wt<<<(128 * 256 + 255) / 256, 256>>>(proj_W, whi + OFF_PROJ, wlo + OFF_PROJ, 128, 256);
    cvt_wt_gat<<<(6 * 65536 + 255) / 256, 256>>>(gat_W, whi + OFF_GAT, wlo + OFF_GAT);
    cvt_wt<<<(256 * 128 + 255) / 256, 256>>>(sem_W1, whi + OFF_SEM, wlo + OFF_SEM, 256, 128);
    cvt_wt<<<(256 * 128 + 255) / 256, 256>>>(cls_W1, whi + OFF_CLS, wlo + OFF_CLS, 256, 128);
    cvt_split<<<(NN * 128 + 255) / 256, 256>>>(x, xhi, xlo, NN * 128);
    for (int p = 0; p < 3; p++)
        init_layer<<<(NN * 64 + 255) / 256, 256>>>(aggB + (size_t)p * NN * 256,
                                                   ssrcB + p * NN * NH,
                                                   sdstB + p * NN * NH,
                                                   denomB + p * NN * NH);

    const int aggrBlocks = (EE * 32) / 256;            // 100000
    const int warpNodeBlocks = (NN * 32 + 255) / 256;  // 6250
    const dim3 gProj(2, (NN + 127) / 128);
    const dim3 gGat(2, (NN + 127) / 128);
    const dim3 gSem(1, (3 * NN + 127) / 128);
    const dim3 gCls(1, (NN + 127) / 128);

    // proj: h0(hi/lo) = x @ proj_W + proj_b
    gemm_mma<1, 0><<<gProj, 256, SMEMSZ>>>(xhi, xlo, whi + OFF_PROJ, wlo + OFF_PROJ,
                                           proj_b, nullptr, h0hi, h0lo,
                                           nullptr, nullptr, nullptr, nullptr, nullptr,
                                           NN, 128, 256);

    // ---- fork: 3 independent metapath chains on 3 streams ----
    cudaEventRecord(evFork, 0);
    for (int p = 0; p < 3; p++) {
        cudaStreamWaitEvent(st[p], evFork, 0);
        const int* srcp = edges + (size_t)p * 2 * EE;
        const int* dstp = srcp + EE;
        float*  agg   = aggB   + (size_t)p * NN * 256;
        float*  ssrc  = ssrcB  + p * NN * NH;
        float*  sdst  = sdstB  + p * NN * NH;
        float*  denom = denomB + p * NN * NH;
        __half* hp16  = hp16B  + (size_t)p * NN * 256;
        __nv_bfloat16* hhi = hhiB + (size_t)p * NN * 256;
        __nv_bfloat16* hlo = hloB + (size_t)p * NN * 256;
        for (int l = 0; l < 2; l++) {
            const int pl = p * 2 + l;
            const __nv_bfloat16* Ah = (l == 0) ? h0hi : hhi;
            const __nv_bfloat16* Al = (l == 0) ? h0lo : hlo;
            gemm_mma<2, 0><<<gGat, 256, SMEMSZ, st[p]>>>(
                Ah, Al, whi + OFF_GAT + pl * 65536, wlo + OFF_GAT + pl * 65536,
                nullptr, nullptr, nullptr, nullptr,
                hp16, gat_asrc + pl * 256, gat_adst + pl * 256, ssrc, sdst,
                NN, 256, 256);
            edge_fused<<<aggrBlocks, 256, 0, st[p]>>>(srcp, dstp, ssrc, sdst, hp16,
                                                      denom, agg);
            if (l == 0) {
                finalize_elu<<<NN, 256, 0, st[p]>>>(agg, denom, ssrc, sdst, hp16,
                                                    gat_b + pl * 256, nullptr,
                                                    hhi, hlo, 256);
            } else {
                finalize_elu<<<NN, 256, 0, st[p]>>>(agg, denom, ssrc, sdst, hp16,
                                                    gat_b + pl * 256,
                                                    emb + p * 256, ehi + p * 256,
                                                    elo + p * 256, 768);
            }
        }
        cudaEventRecord(evJoin[p], st[p]);
    }
    for (int p = 0; p < 3; p++) cudaStreamWaitEvent(0, evJoin[p], 0);

    // ---- epilogue on default stream ----
    gemm_mma<0, 1><<<gSem, 256, SMEMSZ>>>(ehi, elo, whi + OFF_SEM, wlo + OFF_SEM,
                                          sem_b1, hid, nullptr, nullptr,
                                          nullptr, nullptr, nullptr, nullptr, nullptr,
                                          3 * NN, 256, 128);
    sem_kernel<<<warpNodeBlocks, 256>>>(hid, sem_W2, emb, zhi, zlo);

    gemm_mma<0, 2><<<gCls, 256, SMEMSZ>>>(zhi, zlo, whi + OFF_CLS, wlo + OFF_CLS,
                                          cls_b1, hcls, nullptr, nullptr,
                                          nullptr, nullptr, nullptr, nullptr, nullptr,
                                          NN, 256, 128);
    cls_final<<<warpNodeBlocks, 256>>>(hcls, cls_W2, cls_b2, out);
}

// round 16
// speedup vs baseline: 1.0310x; 1.0069x over previous
#include <cuda_runtime.h>
#include <cuda_bf16.h>
#include <cuda_fp16.h>
#include <math.h>
#include <cstdint>

#define NN 50000
#define EE 800000
#define NH 8

// ---------------- scratch (device globals; per-metapath where needed) ----------------
__device__ __align__(16) float g_agg  [3][NN * 256];
__device__ __align__(16) float g_ssrc [3][NN * NH];
__device__ __align__(16) float g_sdst [3][NN * NH];
__device__ __align__(16) float g_denom[3][NN * NH];
__device__ float g_emb  [NN * 3 * 256];
__device__ float g_hid  [NN * 3 * 128];
__device__ float g_hcls [NN * 128];

__device__ __align__(16) __half g_hp16[3][NN * 256];

__device__ __align__(16) __nv_bfloat16 g_xhi [NN * 128];
__device__ __align__(16) __nv_bfloat16 g_xlo [NN * 128];
__device__ __align__(16) __nv_bfloat16 g_h0hi[NN * 256];
__device__ __align__(16) __nv_bfloat16 g_h0lo[NN * 256];
__device__ __align__(16) __nv_bfloat16 g_hhi [3][NN * 256];
__device__ __align__(16) __nv_bfloat16 g_hlo [3][NN * 256];
__device__ __align__(16) __nv_bfloat16 g_ehi [NN * 3 * 256];
__device__ __align__(16) __nv_bfloat16 g_elo [NN * 3 * 256];
__device__ __align__(16) __nv_bfloat16 g_zhi [NN * 256];
__device__ __align__(16) __nv_bfloat16 g_zlo [NN * 256];
// transposed+split weights [N][K]
__device__ __align__(16) __nv_bfloat16 g_whi [491520];
__device__ __align__(16) __nv_bfloat16 g_wlo [491520];

// ---------------- warp-MMA + cp.async helpers (plain sm_80+ PTX) ----------------
__device__ __forceinline__ uint32_t smem_u32(const void* p) {
    uint32_t a;
    asm("{ .reg .u64 t; cvta.to.shared.u64 t, %1; cvt.u32.u64 %0, t; }" : "=r"(a) : "l"(p));
    return a;
}
__device__ __forceinline__ void ldsm_x4(uint32_t* r, uint32_t addr) {
    asm volatile("ldmatrix.sync.aligned.m8n8.x4.shared.b16 {%0,%1,%2,%3}, [%4];"
                 : "=r"(r[0]), "=r"(r[1]), "=r"(r[2]), "=r"(r[3]) : "r"(addr));
}
__device__ __forceinline__ void ldsm_x2(uint32_t* r, uint32_t addr) {
    asm volatile("ldmatrix.sync.aligned.m8n8.x2.shared.b16 {%0,%1}, [%2];"
                 : "=r"(r[0]), "=r"(r[1]) : "r"(addr));
}
__device__ __forceinline__ void mma_bf16(float* c, const uint32_t* a, const uint32_t* b) {
    asm volatile("mma.sync.aligned.m16n8k16.row.col.f32.bf16.bf16.f32 "
                 "{%0,%1,%2,%3}, {%4,%5,%6,%7}, {%8,%9}, {%0,%1,%2,%3};"
                 : "+f"(c[0]), "+f"(c[1]), "+f"(c[2]), "+f"(c[3])
                 : "r"(a[0]), "r"(a[1]), "r"(a[2]), "r"(a[3]), "r"(b[0]), "r"(b[1]));
}
__device__ __forceinline__ void cp16(uint32_t saddr, const void* g, int srcsize) {
    asm volatile("cp.async.cg.shared.global [%0], [%1], 16, %2;"
                 :: "r"(saddr), "l"(g), "r"(srcsize) : "memory");
}
#define CP_COMMIT() asm volatile("cp.async.commit_group;" ::: "memory")
#define CP_WAIT(n)  asm volatile("cp.async.wait_group %0;" :: "n"(n) : "memory")
__device__ __forceinline__ void red_add_v2(float* p, float x, float y) {
    asm volatile("red.global.add.v2.f32 [%0], {%1, %2};"
                 :: "l"(p), "f"(x), "f"(y) : "memory");
}

// ---------------- bf16-split tensor GEMM, cp.async double-buffered ----------------
#define LDSE   40
#define PLANE  10240
#define BUFSZ  20480
#define BHALF  40960
#define SMEMSZ 81920
template <int EPI, int ACT>   // EPI: 0 fp32 C, 1 split bf16 C, 2 GAT. ACT: 0/1 tanh/2 relu
__global__ void __launch_bounds__(256, 1)
gemm_mma(const __nv_bfloat16* __restrict__ Ahi, const __nv_bfloat16* __restrict__ Alo,
         const __nv_bfloat16* __restrict__ Bhi, const __nv_bfloat16* __restrict__ Blo,
         const float* __restrict__ bias,
         float* __restrict__ C, __nv_bfloat16* __restrict__ Chi,
         __nv_bfloat16* __restrict__ Clo,
         __half* __restrict__ H16,
         const float* __restrict__ asrc, const float* __restrict__ adst,
         float* __restrict__ Ssrc, float* __restrict__ Sdst,
         int M, int K, int Nc) {
    extern __shared__ __align__(16) char smem[];
    const uint32_t sAu = smem_u32(smem);
    const uint32_t sBu = sAu + BHALF;
    const int tid = threadIdx.x;
    const int lane = tid & 31;
    const int w = tid >> 5;
    const int wm = w & 3, wn = w >> 2;
    const int rowBase = blockIdx.y * 128;
    const int colBase = blockIdx.x * 128;

    float acc[2][8][4];
#pragma unroll
    for (int i = 0; i < 2; i++)
#pragma unroll
        for (int j = 0; j < 8; j++)
#pragma unroll
            for (int e = 0; e < 4; e++) acc[i][j][e] = 0.f;

    auto load_tile = [&](int buf, int k0) {
#pragma unroll
        for (int t = 0; t < 2; t++) {
            const int idx = tid + t * 256;
            const int row = idx >> 2;
            const int cb  = (idx & 3) * 16;
            const uint32_t soff = (uint32_t)(row * (LDSE * 2) + cb);
            const int grow = rowBase + row;
            const int ar = grow < M ? grow : (M - 1);
            const int ssz = grow < M ? 16 : 0;
            const char* gah = (const char*)Ahi + ((size_t)ar * K + k0) * 2 + cb;
            const char* gal = (const char*)Alo + ((size_t)ar * K + k0) * 2 + cb;
            cp16(sAu + buf * BUFSZ + soff,          gah, ssz);
            cp16(sAu + buf * BUFSZ + PLANE + soff,  gal, ssz);
            const int gn = colBase + row;
            const char* gbh = (const char*)Bhi + ((size_t)gn * K + k0) * 2 + cb;
            const char* gbl = (const char*)Blo + ((size_t)gn * K + k0) * 2 + cb;
            cp16(sBu + buf * BUFSZ + soff,          gbh, 16);
            cp16(sBu + buf * BUFSZ + PLANE + soff,  gbl, 16);
        }
    };

    const int ntiles = K >> 5;
    load_tile(0, 0);
    CP_COMMIT();

    for (int c = 0; c < ntiles; c++) {
        const int cur = c & 1;
        if (c + 1 < ntiles) {
            load_tile(cur ^ 1, (c + 1) << 5);
            CP_COMMIT();
            CP_WAIT(1);
        } else {
            CP_WAIT(0);
        }
        __syncthreads();

        const uint32_t aB = sAu + cur * BUFSZ;
        const uint32_t bB = sBu + cur * BUFSZ;
#pragma unroll
        for (int k16 = 0; k16 < 2; k16++) {
            uint32_t ahi[2][4], alo[2][4];
#pragma unroll
            for (int mt = 0; mt < 2; mt++) {
                const uint32_t ra = aB +
                    (uint32_t)((wm * 32 + mt * 16 + (lane & 15)) * (LDSE * 2)
                               + k16 * 32 + (lane >> 4) * 16);
                ldsm_x4(ahi[mt], ra);
                ldsm_x4(alo[mt], ra + PLANE);
            }
#pragma unroll
            for (int nt = 0; nt < 8; nt++) {
                const uint32_t rb = bB +
                    (uint32_t)((wn * 64 + nt * 8 + (lane & 7)) * (LDSE * 2)
                               + k16 * 32 + ((lane >> 3) & 1) * 16);
                uint32_t bhi[2], blo[2];
                ldsm_x2(bhi, rb);
                ldsm_x2(blo, rb + PLANE);
#pragma unroll
                for (int mt = 0; mt < 2; mt++) {
                    mma_bf16(acc[mt][nt], ahi[mt], bhi);
                    mma_bf16(acc[mt][nt], ahi[mt], blo);
                    mma_bf16(acc[mt][nt], alo[mt], bhi);
                }
            }
        }
        __syncthreads();
    }

    const int g = lane >> 2, tq = lane & 3;
    if (EPI == 2) {
        const int headbase = blockIdx.x * 4 + wn * 2;
#pragma unroll
        for (int mt = 0; mt < 2; mt++) {
#pragma unroll
            for (int half = 0; half < 2; half++) {
                const int row = rowBase + wm * 32 + mt * 16 + g + half * 8;
                float ps0 = 0.f, ps1 = 0.f, pd0 = 0.f, pd1 = 0.f;
                if (row < M) {
#pragma unroll
                    for (int nt = 0; nt < 8; nt++) {
                        const int col = colBase + wn * 64 + nt * 8 + tq * 2;
                        const float v0 = acc[mt][nt][half * 2 + 0];
                        const float v1 = acc[mt][nt][half * 2 + 1];
                        *(__half2*)(H16 + (size_t)row * 256 + col) =
                            __floats2half2_rn(v0, v1);
                        const float a0s = __ldg(&asrc[col]), a1s = __ldg(&asrc[col + 1]);
                        const float a0d = __ldg(&adst[col]), a1d = __ldg(&adst[col + 1]);
                        if (nt < 4) { ps0 += v0 * a0s + v1 * a1s; pd0 += v0 * a0d + v1 * a1d; }
                        else        { ps1 += v0 * a0s + v1 * a1s; pd1 += v0 * a0d + v1 * a1d; }
                    }
                }
                ps0 += __shfl_down_sync(0xffffffffu, ps0, 2);
                ps0 += __shfl_down_sync(0xffffffffu, ps0, 1);
                ps1 += __shfl_down_sync(0xffffffffu, ps1, 2);
                ps1 += __shfl_down_sync(0xffffffffu, ps1, 1);
                pd0 += __shfl_down_sync(0xffffffffu, pd0, 2);
                pd0 += __shfl_down_sync(0xffffffffu, pd0, 1);
                pd1 += __shfl_down_sync(0xffffffffu, pd1, 2);
                pd1 += __shfl_down_sync(0xffffffffu, pd1, 1);
                if (tq == 0 && row < M) {
                    atomicAdd(&Ssrc[row * NH + headbase + 0], ps0);
                    atomicAdd(&Ssrc[row * NH + headbase + 1], ps1);
                    atomicAdd(&Sdst[row * NH + headbase + 0], pd0);
                    atomicAdd(&Sdst[row * NH + headbase + 1], pd1);
                }
            }
        }
    } else {
#pragma unroll
        for (int mt = 0; mt < 2; mt++) {
#pragma unroll
            for (int nt = 0; nt < 8; nt++) {
                const int col = colBase + wn * 64 + nt * 8 + tq * 2;
#pragma unroll
                for (int half = 0; half < 2; half++) {
                    const int row = rowBase + wm * 32 + mt * 16 + g + half * 8;
                    if (row < M) {
#pragma unroll
                        for (int e = 0; e < 2; e++) {
                            float v = acc[mt][nt][half * 2 + e];
                            const int c = col + e;
                            if (bias) v += bias[c];
                            if (ACT == 1) v = tanhf(v);
                            else if (ACT == 2) v = fmaxf(v, 0.f);
                            const size_t o = (size_t)row * Nc + c;
                            if (EPI == 1) {
                                const __nv_bfloat16 h = __float2bfloat16(v);
                                Chi[o] = h;
                                Clo[o] = __float2bfloat16(v - __bfloat162float(h));
                            } else {
                                C[o] = v;
                            }
                        }
                    }
                }
            }
        }
    }
}

// ---------------- weight transpose + split ----------------
__global__ void cvt_wt(const float* __restrict__ W, __nv_bfloat16* __restrict__ hi,
                       __nv_bfloat16* __restrict__ lo, int K, int N) {
    const int i = blockIdx.x * blockDim.x + threadIdx.x;
    if (i >= K * N) return;
    const int n = i / K, k = i % K;
    const float v = W[k * N + n];
    const __nv_bfloat16 h = __float2bfloat16(v);
    hi[i] = h;
    lo[i] = __float2bfloat16(v - __bfloat162float(h));
}
__global__ void cvt_wt_gat(const float* __restrict__ W, __nv_bfloat16* __restrict__ hi,
                           __nv_bfloat16* __restrict__ lo) {
    const int i = blockIdx.x * blockDim.x + threadIdx.x;
    if (i >= 6 * 65536) return;
    const int pl = i >> 16, r = i & 65535;
    const int n = r / 256, k = r % 256;
    const float v = W[(size_t)pl * 65536 + k * 256 + n];
    const __nv_bfloat16 h = __float2bfloat16(v);
    hi[i] = h;
    lo[i] = __float2bfloat16(v - __bfloat162float(h));
}
__global__ void cvt_split(const float* __restrict__ in, __nv_bfloat16* __restrict__ hi,
                          __nv_bfloat16* __restrict__ lo, int n) {
    const int i = blockIdx.x * blockDim.x + threadIdx.x;
    if (i >= n) return;
    const float v = in[i];
    const __nv_bfloat16 h = __float2bfloat16(v);
    hi[i] = h;
    lo[i] = __float2bfloat16(v - __bfloat162float(h));
}

// ---------------- zero init for one metapath's accumulators ----------------
__global__ void init_layer(float* __restrict__ agg, float* __restrict__ ssrc,
                           float* __restrict__ sdst, float* __restrict__ denom) {
    const int i = blockIdx.x * blockDim.x + threadIdx.x;   // NN*64 (float4)
    if (i >= NN * 64) return;
    ((float4*)agg)[i] = make_float4(0.f, 0.f, 0.f, 0.f);
    if (i < NN * 2) {
        ((float4*)ssrc)[i]  = make_float4(0.f, 0.f, 0.f, 0.f);
        ((float4*)sdst)[i]  = make_float4(0.f, 0.f, 0.f, 0.f);
        ((float4*)denom)[i] = make_float4(0.f, 0.f, 0.f, 0.f);
    }
}

// ---------------- fused edge pass: half2 gather + red.v2 scatter (coalesced) ----------------
// One warp per edge. Iteration i covers elements [i*64, i*64+64); lane owns pair j=i*64+lane*2
// (pairs never straddle a 32-wide head boundary; alpha = shfl(ex, j>>5)).
__global__ void edge_fused(const int* __restrict__ src, const int* __restrict__ dst,
                           const float* __restrict__ s_src, const float* __restrict__ s_dst,
                           const __half* __restrict__ hp16,
                           float* __restrict__ denom, float* __restrict__ agg) {
    const int gw = (blockIdx.x * blockDim.x + threadIdx.x) >> 5;
    const int lane = threadIdx.x & 31;
    if (gw >= EE) return;
    const int s = __ldg(&src[gw]);
    const int d = __ldg(&dst[gw]);
    float ex = 0.f;
    if (lane < 8) {
        const float zz = __ldg(&s_src[s * NH + lane]) + __ldg(&s_dst[d * NH + lane]);
        const float e = zz > 0.f ? zz : 0.2f * zz;
        ex = __expf(e);
        atomicAdd(&denom[d * NH + lane], ex);
    }
    const __half* rowp = hp16 + (size_t)s * 256;
    float* aggp = agg + (size_t)d * 256;
#pragma unroll
    for (int i = 0; i < 4; i++) {
        const int j = i * 64 + lane * 2;
        const float al = __shfl_sync(0xffffffffu, ex, j >> 5);
        const float2 f = __half22float2(__ldg((const __half2*)(rowp + j)));
        red_add_v2(aggp + j, al * f.x, al * f.y);
    }
}

// ---------------- finalize: self-loop + normalize + bias + ELU + zero for next layer ----
__global__ void finalize_elu(float* __restrict__ agg, float* __restrict__ denom,
                             float* __restrict__ ssrc, float* __restrict__ sdst,
                             const __half* __restrict__ hp16,
                             const float* __restrict__ b,
                             float* __restrict__ outf,
                             __nv_bfloat16* __restrict__ ohi,
                             __nv_bfloat16* __restrict__ olo,
                             int rowStride) {
    const int n = blockIdx.x;
    const int t = threadIdx.x;
    const int h = t >> 5;
    const float zz = ssrc[n * NH + h] + sdst[n * NH + h];
    const float le = zz > 0.f ? zz : 0.2f * zz;
    const float exs = __expf(le);
    const float hpv = __half2float(hp16[n * 256 + t]);
    float v = (agg[n * 256 + t] + exs * hpv) / (denom[n * NH + h] + exs) + b[t];
    v = v > 0.f ? v : expm1f(v);
    const size_t o = (size_t)n * rowStride + t;
    if (outf) outf[o] = v;
    const __nv_bfloat16 hh = __float2bfloat16(v);
    ohi[o] = hh;
    olo[o] = __float2bfloat16(v - __bfloat162float(hh));
    __syncthreads();
    agg[n * 256 + t] = 0.f;
    if (t < NH) {
        ssrc[n * NH + t]  = 0.f;
        sdst[n * NH + t]  = 0.f;
        denom[n * NH + t] = 0.f;
    }
}

// ---------------- semantic attention; emit z as bf16 hi/lo ----------------
__global__ void sem_kernel(const float* __restrict__ hid, const float* __restrict__ W2,
                           const float* __restrict__ emb,
                           __nv_bfloat16* __restrict__ zhi,
                           __nv_bfloat16* __restrict__ zlo) {
    const int warp = (blockIdx.x * blockDim.x + threadIdx.x) >> 5;
    const int lane = threadIdx.x & 31;
    if (warp >= NN) return;
    float sc[3];
#pragma unroll
    for (int p = 0; p < 3; p++) {
        float part = 0.f;
#pragma unroll
        for (int t = lane; t < 128; t += 32)
            part += hid[(size_t)(warp * 3 + p) * 128 + t] * W2[t];
#pragma unroll
        for (int o = 16; o > 0; o >>= 1) part += __shfl_down_sync(0xffffffffu, part, o);
        sc[p] = __shfl_sync(0xffffffffu, part, 0);
    }
    const float mx = fmaxf(sc[0], fmaxf(sc[1], sc[2]));
    const float e0 = __expf(sc[0] - mx), e1 = __expf(sc[1] - mx), e2 = __expf(sc[2] - mx);
    const float inv = 1.f / (e0 + e1 + e2);
    const float w0 = e0 * inv, w1 = e1 * inv, w2 = e2 * inv;
    const float* er = &emb[(size_t)warp * 768];
#pragma unroll
    for (int j = lane; j < 256; j += 32) {
        const float v = w0 * er[j] + w1 * er[256 + j] + w2 * er[512 + j];
        const __nv_bfloat16 h = __float2bfloat16(v);
        zhi[(size_t)warp * 256 + j] = h;
        zlo[(size_t)warp * 256 + j] = __float2bfloat16(v - __bfloat162float(h));
    }
}

// ---------------- classifier head ----------------
__global__ void cls_final(const float* __restrict__ hcls, const float* __restrict__ W2,
                          const float* __restrict__ b2, float* __restrict__ out) {
    const int warp = (blockIdx.x * blockDim.x + threadIdx.x) >> 5;
    const int lane = threadIdx.x & 31;
    if (warp >= NN) return;
    float p0 = 0.f, p1 = 0.f;
#pragma unroll
    for (int t = lane; t < 128; t += 32) {
        const float v = hcls[(size_t)warp * 128 + t];
        p0 += v * W2[t * 2 + 0];
        p1 += v * W2[t * 2 + 1];
    }
#pragma unroll
    for (int o = 16; o > 0; o >>= 1) {
        p0 += __shfl_down_sync(0xffffffffu, p0, o);
        p1 += __shfl_down_sync(0xffffffffu, p1, o);
    }
    if (lane == 0) {
        out[(size_t)warp * 2 + 0] = p0 + b2[0];
        out[(size_t)warp * 2 + 1] = p1 + b2[1];
    }
}

extern "C" void kernel_launch(void* const* d_in, const int* in_sizes, int n_in,
                              void* d_out, int out_size) {
    const float* x        = (const float*)d_in[0];
    const int*   edges    = (const int*)  d_in[1];
    const float* proj_W   = (const float*)d_in[2];
    const float* proj_b   = (const float*)d_in[3];
    const float* gat_W    = (const float*)d_in[4];
    const float* gat_asrc = (const float*)d_in[5];
    const float* gat_adst = (const float*)d_in[6];
    const float* gat_b    = (const float*)d_in[7];
    const float* sem_W1   = (const float*)d_in[8];
    const float* sem_b1   = (const float*)d_in[9];
    const float* sem_W2   = (const float*)d_in[10];
    const float* cls_W1   = (const float*)d_in[11];
    const float* cls_b1   = (const float*)d_in[12];
    const float* cls_W2   = (const float*)d_in[13];
    const float* cls_b2   = (const float*)d_in[14];
    float* out = (float*)d_out;

    float *aggB, *ssrcB, *sdstB, *denomB, *emb, *hid, *hcls;
    __half* hp16B;
    __nv_bfloat16 *xhi, *xlo, *h0hi, *h0lo, *hhiB, *hloB, *ehi, *elo, *zhi, *zlo, *whi, *wlo;
    cudaGetSymbolAddress((void**)&aggB,  g_agg);
    cudaGetSymbolAddress((void**)&ssrcB, g_ssrc);
    cudaGetSymbolAddress((void**)&sdstB, g_sdst);
    cudaGetSymbolAddress((void**)&denomB,g_denom);
    cudaGetSymbolAddress((void**)&emb,   g_emb);
    cudaGetSymbolAddress((void**)&hid,   g_hid);
    cudaGetSymbolAddress((void**)&hcls,  g_hcls);
    cudaGetSymbolAddress((void**)&hp16B, g_hp16);
    cudaGetSymbolAddress((void**)&xhi,   g_xhi);
    cudaGetSymbolAddress((void**)&xlo,   g_xlo);
    cudaGetSymbolAddress((void**)&h0hi,  g_h0hi);
    cudaGetSymbolAddress((void**)&h0lo,  g_h0lo);
    cudaGetSymbolAddress((void**)&hhiB,  g_hhi);
    cudaGetSymbolAddress((void**)&hloB,  g_hlo);
    cudaGetSymbolAddress((void**)&ehi,   g_ehi);
    cudaGetSymbolAddress((void**)&elo,   g_elo);
    cudaGetSymbolAddress((void**)&zhi,   g_zhi);
    cudaGetSymbolAddress((void**)&zlo,   g_zlo);
    cudaGetSymbolAddress((void**)&whi,   g_whi);
    cudaGetSymbolAddress((void**)&wlo,   g_wlo);

    cudaFuncSetAttribute(gemm_mma<1, 0>, cudaFuncAttributeMaxDynamicSharedMemorySize, SMEMSZ);
    cudaFuncSetAttribute(gemm_mma<2, 0>, cudaFuncAttributeMaxDynamicSharedMemorySize, SMEMSZ);
    cudaFuncSetAttribute(gemm_mma<0, 1>, cudaFuncAttributeMaxDynamicSharedMemorySize, SMEMSZ);
    cudaFuncSetAttribute(gemm_mma<0, 2>, cudaFuncAttributeMaxDynamicSharedMemorySize, SMEMSZ);

    // persistent streams/events for the 3 metapath chains (created once; no device mem)
    static cudaStream_t st[3] = {nullptr, nullptr, nullptr};
    static cudaEvent_t evFork = nullptr, evJoin[3] = {nullptr, nullptr, nullptr};
    if (!st[0]) {
        for (int p = 0; p < 3; p++) {
            cudaStreamCreateWithFlags(&st[p], cudaStreamNonBlocking);
            cudaEventCreateWithFlags(&evJoin[p], cudaEventDisableTiming);
        }
        cudaEventCreateWithFlags(&evFork, cudaEventDisableTiming);
    }

    const int OFF_PROJ = 0;
    const int OFF_GAT  = 32768;
    const int OFF_SEM  = 32768 + 6 * 65536;
    const int OFF_CLS  = OFF_SEM + 32768;

    // ---- prologue on capture-origin (default) stream ----
    cvt_wt<<<(128 * 256 + 255) / 256, 256>>>(proj_W, whi + OFF_PROJ, wlo + OFF_PROJ, 128, 256);
    cvt_wt_gat<<<(6 * 65536 + 255) / 256, 256>>>(gat_W, whi + OFF_GAT, wlo + OFF_GAT);
    cvt_wt<<<(256 * 128 + 255) / 256, 256>>>(sem_W1, whi + OFF_SEM, wlo + OFF_SEM, 256, 128);
    cvt_wt<<<(256 * 128 + 255) / 256, 256>>>(cls_W1, whi + OFF_CLS, wlo + OFF_CLS, 256, 128);
    cvt_split<<<(NN * 128 + 255) / 256, 256>>>(x, xhi, xlo, NN * 128);
    for (int p = 0; p < 3; p++)
        init_layer<<<(NN * 64 + 255) / 256, 256>>>(aggB + (size_t)p * NN * 256,
                                                   ssrcB + p * NN * NH,
                                                   sdstB + p * NN * NH,
                                                   denomB + p * NN * NH);

    const int aggrBlocks = (EE * 32) / 256;            // 100000
    const int warpNodeBlocks = (NN * 32 + 255) / 256;  // 6250
    const dim3 gProj(2, (NN + 127) / 128);
    const dim3 gGat(2, (NN + 127) / 128);
    const dim3 gSem(1, (3 * NN + 127) / 128);
    const dim3 gCls(1, (NN + 127) / 128);

    // proj: h0(hi/lo) = x @ proj_W + proj_b
    gemm_mma<1, 0><<<gProj, 256, SMEMSZ>>>(xhi, xlo, whi + OFF_PROJ, wlo + OFF_PROJ,
                                           proj_b, nullptr, h0hi, h0lo,
                                           nullptr, nullptr, nullptr, nullptr, nullptr,
                                           NN, 128, 256);

    // ---- fork: 3 independent metapath chains on 3 streams ----
    cudaEventRecord(evFork, 0);
    for (int p = 0; p < 3; p++) {
        cudaStreamWaitEvent(st[p], evFork, 0);
        const int* srcp = edges + (size_t)p * 2 * EE;
        const int* dstp = srcp + EE;
        float*  agg   = aggB   + (size_t)p * NN * 256;
        float*  ssrc  = ssrcB  + p * NN * NH;
        float*  sdst  = sdstB  + p * NN * NH;
        float*  denom = denomB + p * NN * NH;
        __half* hp16  = hp16B  + (size_t)p * NN * 256;
        __nv_bfloat16* hhi = hhiB + (size_t)p * NN * 256;
        __nv_bfloat16* hlo = hloB + (size_t)p * NN * 256;
        for (int l = 0; l < 2; l++) {
            const int pl = p * 2 + l;
            const __nv_bfloat16* Ah = (l == 0) ? h0hi : hhi;
            const __nv_bfloat16* Al = (l == 0) ? h0lo : hlo;
            gemm_mma<2, 0><<<gGat, 256, SMEMSZ, st[p]>>>(
                Ah, Al, whi + OFF_GAT + pl * 65536, wlo + OFF_GAT + pl * 65536,
                nullptr, nullptr, nullptr, nullptr,
                hp16, gat_asrc + pl * 256, gat_adst + pl * 256, ssrc, sdst,
                NN, 256, 256);
            edge_fused<<<aggrBlocks, 256, 0, st[p]>>>(srcp, dstp, ssrc, sdst, hp16,
                                                      denom, agg);
            if (l == 0) {
                finalize_elu<<<NN, 256, 0, st[p]>>>(agg, denom, ssrc, sdst, hp16,
                                                    gat_b + pl * 256, nullptr,
                                                    hhi, hlo, 256);
            } else {
                finalize_elu<<<NN, 256, 0, st[p]>>>(agg, denom, ssrc, sdst, hp16,
                                                    gat_b + pl * 256,
                                                    emb + p * 256, ehi + p * 256,
                                                    elo + p * 256, 768);
            }
        }
        cudaEventRecord(evJoin[p], st[p]);
    }
    for (int p = 0; p < 3; p++) cudaStreamWaitEvent(0, evJoin[p], 0);

    // ---- epilogue on default stream ----
    gemm_mma<0, 1><<<gSem, 256, SMEMSZ>>>(ehi, elo, whi + OFF_SEM, wlo + OFF_SEM,
                                          sem_b1, hid, nullptr, nullptr,
                                          nullptr, nullptr, nullptr, nullptr, nullptr,
                                          3 * NN, 256, 128);
    sem_kernel<<<warpNodeBlocks, 256>>>(hid, sem_W2, emb, zhi, zlo);

    gemm_mma<0, 2><<<gCls, 256, SMEMSZ>>>(zhi, zlo, whi + OFF_CLS, wlo + OFF_CLS,
                                          cls_b1, hcls, nullptr, nullptr,
                                          nullptr, nullptr, nullptr, nullptr, nullptr,
                                          NN, 256, 128);
    cls_final<<<warpNodeBlocks, 256>>>(hcls, cls_W2, cls_b2, out);
}